// round 2
// baseline (speedup 1.0000x reference)
#include <cuda_runtime.h>
#include <cuda_bf16.h>

// Problem constants
#define BATCH 32
#define NN    1024          // N (nodes / feature dim of sc rows)
#define DD    512           // hidden dim
#define LN_EPS 1e-5f

// GEMM tile config
#define BM 128
#define BN 128
#define BK 16

// ---------------------------------------------------------------------------
// Scratch (device globals; no allocation allowed in kernel_launch)
// ---------------------------------------------------------------------------
__device__ float g_buf0[(size_t)BATCH * NN * DD];    // 64 MB
__device__ float g_buf1[(size_t)BATCH * NN * DD];    // 64 MB
__device__ float g_dis[BATCH * NN];
__device__ float g_partial[BATCH * 8 * DD];          // LN+pool partials

// ---------------------------------------------------------------------------
// 1) dis[b,j] = rsqrt( sum_i A[b,i,j] )   (column sums of A)
// ---------------------------------------------------------------------------
__global__ void deg_kernel(const float* __restrict__ A, float* __restrict__ dis)
{
    int b = blockIdx.y;
    int j = blockIdx.x * 256 + threadIdx.x;
    const float* Ab = A + (size_t)b * NN * NN;
    float s = 0.f;
#pragma unroll 8
    for (int i = 0; i < NN; i++)
        s += Ab[(size_t)i * NN + j];
    dis[b * NN + j] = (s > 0.f) ? rsqrtf(s) : 0.f;
}

// ---------------------------------------------------------------------------
// Tiled SGEMM.
//   TRANSA=0 : A[m*lda + k]     (row-major A)
//   TRANSA=1 : A[k*lda + m]     (computes A_stored^T @ B; coalesced row loads)
//   B is always B[k*ldb + n].
// Epilogue:
//   EPI=0 : C = acc * dis[m]
//   EPI=1 : C = relu(acc * dis[m] + bias[n])
//   EPI=2 : C = acc * dis[m] + bias[n]
// blockIdx.z = batch index; strides advance base pointers per batch.
// All dims are exact multiples of the tile sizes (checked on host side).
// ---------------------------------------------------------------------------
template<int TRANSA, int EPI>
__global__ void __launch_bounds__(256, 2) gemm_k(
    const float* __restrict__ A, const float* __restrict__ Bm, float* __restrict__ C,
    int K, int lda, int ldb, int ldc,
    long sA, long sB, long sC,
    const float* __restrict__ dis, int sDis,
    const float* __restrict__ bias)
{
    int bz = blockIdx.z;
    A   += (long)bz * sA;
    Bm  += (long)bz * sB;
    C   += (long)bz * sC;
    dis += (long)bz * sDis;

    const int m0 = blockIdx.y * BM;
    const int n0 = blockIdx.x * BN;
    const int tid = threadIdx.x;
    const int tx = tid & 15;
    const int ty = tid >> 4;

    __shared__ float As[BK][BM];
    __shared__ float Bs[BK][BN];

    float acc[8][8];
#pragma unroll
    for (int i = 0; i < 8; i++)
#pragma unroll
        for (int j = 0; j < 8; j++) acc[i][j] = 0.f;

    for (int k0 = 0; k0 < K; k0 += BK) {
        // ---- load A tile into As[k][m] ----
        if (TRANSA) {
            // stored A[k*lda + m]: 16 rows x 128 cols, direct vector copy
#pragma unroll
            for (int r = 0; r < 2; r++) {
                int idx = tid + r * 256;          // 0..511 float4s
                int kr  = idx >> 5;               // 0..15
                int mc  = (idx & 31) << 2;        // 0..124
                float4 v = *reinterpret_cast<const float4*>(
                    &A[(long)(k0 + kr) * lda + m0 + mc]);
                *reinterpret_cast<float4*>(&As[kr][mc]) = v;
            }
        } else {
            // stored A[m*lda + k]: 128 rows x 16 cols, transpose into As
#pragma unroll
            for (int r = 0; r < 2; r++) {
                int idx = tid + r * 256;
                int mr  = idx >> 2;               // 0..127
                int kc  = (idx & 3) << 2;         // 0,4,8,12
                float4 v = *reinterpret_cast<const float4*>(
                    &A[(long)(m0 + mr) * lda + k0 + kc]);
                As[kc + 0][mr] = v.x;
                As[kc + 1][mr] = v.y;
                As[kc + 2][mr] = v.z;
                As[kc + 3][mr] = v.w;
            }
        }
        // ---- load B tile: 16 rows x 128 cols ----
#pragma unroll
        for (int r = 0; r < 2; r++) {
            int idx = tid + r * 256;
            int kr  = idx >> 5;
            int nc  = (idx & 31) << 2;
            float4 v = *reinterpret_cast<const float4*>(
                &Bm[(long)(k0 + kr) * ldb + n0 + nc]);
            *reinterpret_cast<float4*>(&Bs[kr][nc]) = v;
        }
        __syncthreads();

#pragma unroll
        for (int kk = 0; kk < BK; kk++) {
            float a[8], b[8];
#pragma unroll
            for (int i = 0; i < 8; i += 4)
                *reinterpret_cast<float4*>(&a[i]) =
                    *reinterpret_cast<const float4*>(&As[kk][ty * 8 + i]);
#pragma unroll
            for (int j = 0; j < 8; j += 4)
                *reinterpret_cast<float4*>(&b[j]) =
                    *reinterpret_cast<const float4*>(&Bs[kk][tx * 8 + j]);
#pragma unroll
            for (int i = 0; i < 8; i++)
#pragma unroll
                for (int j = 0; j < 8; j++)
                    acc[i][j] = fmaf(a[i], b[j], acc[i][j]);
        }
        __syncthreads();
    }

    // ---- epilogue ----
#pragma unroll
    for (int i = 0; i < 8; i++) {
        int m = m0 + ty * 8 + i;
        float dsc = dis[m];
#pragma unroll
        for (int j = 0; j < 8; j++) {
            float v = acc[i][j] * dsc;
            if (EPI >= 1) v += bias[n0 + tx * 8 + j];
            if (EPI == 1) v = fmaxf(v, 0.f);
            acc[i][j] = v;
        }
#pragma unroll
        for (int j = 0; j < 8; j += 4)
            *reinterpret_cast<float4*>(&C[(long)m * ldc + n0 + tx * 8 + j]) =
                *reinterpret_cast<const float4*>(&acc[i][j]);
    }
}

// ---------------------------------------------------------------------------
// 3) LayerNorm each row of h2 [B,N,D] over D, then partial-sum over a chunk of
//    128 rows:  partial[b,ch,d] = ln_g[d]*sum_rows(norm) + 128*ln_b[d]
//    (deterministic two-stage reduction, no atomics)
// grid (8, B), block 256 = 8 warps; each warp owns rows w, w+8, ...
// ---------------------------------------------------------------------------
__global__ void ln_pool_partial(const float* __restrict__ h2,
                                const float* __restrict__ lng,
                                const float* __restrict__ lnb,
                                float* __restrict__ partial)
{
    int b  = blockIdx.y;
    int ch = blockIdx.x;
    int w  = threadIdx.x >> 5;
    int l  = threadIdx.x & 31;
    const float* base = h2 + ((size_t)b * NN + ch * 128) * DD;

    float accv[16];
#pragma unroll
    for (int c = 0; c < 16; c++) accv[c] = 0.f;

    for (int r = w; r < 128; r += 8) {
        const float* row = base + (size_t)r * DD;
        float x[16];
        float s = 0.f;
#pragma unroll
        for (int c = 0; c < 16; c++) { x[c] = row[l + 32 * c]; s += x[c]; }
#pragma unroll
        for (int o = 16; o; o >>= 1) s += __shfl_xor_sync(0xffffffffu, s, o);
        float mu = s * (1.f / DD);
        float s2 = 0.f;
#pragma unroll
        for (int c = 0; c < 16; c++) { float d = x[c] - mu; s2 += d * d; }
#pragma unroll
        for (int o = 16; o; o >>= 1) s2 += __shfl_xor_sync(0xffffffffu, s2, o);
        float rstd = rsqrtf(s2 * (1.f / DD) + LN_EPS);
#pragma unroll
        for (int c = 0; c < 16; c++) accv[c] += (x[c] - mu) * rstd;
    }

    __shared__ float wacc[8][DD];
#pragma unroll
    for (int c = 0; c < 16; c++) wacc[w][l + 32 * c] = accv[c];
    __syncthreads();

    for (int d = threadIdx.x; d < DD; d += 256) {
        float s = 0.f;
#pragma unroll
        for (int w2 = 0; w2 < 8; w2++) s += wacc[w2][d];
        partial[((size_t)b * 8 + ch) * DD + d] = lng[d] * s + 128.f * lnb[d];
    }
}

// z_pooled[b,d] = (1/N) * sum_ch partial[b,ch,d]
__global__ void pool_finalize(const float* __restrict__ partial,
                              float* __restrict__ zp)
{
    int b = blockIdx.x;
    int d = threadIdx.x;      // 512 threads
    float s = 0.f;
#pragma unroll
    for (int c = 0; c < 8; c++) s += partial[((size_t)b * 8 + c) * DD + d];
    zp[b * DD + d] = s * (1.f / NN);
}

// ---------------------------------------------------------------------------
// 4) Classifier head: one block (128 threads) per batch element.
// ---------------------------------------------------------------------------
__device__ __forceinline__ float blk_sum128(float v, volatile float* red)
{
    int t = threadIdx.x;
    red[t] = v;
    __syncthreads();
#pragma unroll
    for (int o = 64; o > 0; o >>= 1) {
        if (t < o) red[t] += red[t + o];
        __syncthreads();
    }
    float s = red[0];
    __syncthreads();
    return s;
}

__global__ void classifier_kernel(
    const float* __restrict__ zp_all,
    const float* __restrict__ Wc1, const float* __restrict__ bc1,
    const float* __restrict__ g1,  const float* __restrict__ t1p,
    const float* __restrict__ Wc2, const float* __restrict__ bc2,
    const float* __restrict__ g2,  const float* __restrict__ t2p,
    const float* __restrict__ Wc3, const float* __restrict__ bc3,
    float* __restrict__ logits)
{
    int b = blockIdx.x;
    int t = threadIdx.x;     // 128 threads
    __shared__ float zp[DD];
    __shared__ float c1[128];
    __shared__ float c2[64];
    __shared__ float red[128];

    for (int d = t; d < DD; d += 128) zp[d] = zp_all[b * DD + d];
    __syncthreads();

    // layer 1: [512]->[128], LN(128), relu
    float v = 0.f;
#pragma unroll 4
    for (int k = 0; k < DD; k++) v = fmaf(zp[k], Wc1[k * 128 + t], v);
    v += bc1[t];
    float mu = blk_sum128(v, red) * (1.f / 128.f);
    float d1 = v - mu;
    float var = blk_sum128(d1 * d1, red) * (1.f / 128.f);
    v = d1 * rsqrtf(var + LN_EPS) * g1[t] + t1p[t];
    v = fmaxf(v, 0.f);
    c1[t] = v;
    __syncthreads();

    // layer 2: [128]->[64], LN(64), relu
    float v2 = 0.f;
    if (t < 64) {
#pragma unroll 4
        for (int k = 0; k < 128; k++) v2 = fmaf(c1[k], Wc2[k * 64 + t], v2);
        v2 += bc2[t];
    }
    float mu2 = blk_sum128((t < 64) ? v2 : 0.f, red) * (1.f / 64.f);
    float d2 = (t < 64) ? (v2 - mu2) : 0.f;
    float var2 = blk_sum128(d2 * d2, red) * (1.f / 64.f);
    if (t < 64) {
        v2 = d2 * rsqrtf(var2 + LN_EPS) * g2[t] + t2p[t];
        v2 = fmaxf(v2, 0.f);
        c2[t] = v2;
    }
    __syncthreads();

    // layer 3: [64]->[4]
    if (t < 4) {
        float s = bc3[t];
#pragma unroll
        for (int k = 0; k < 64; k++) s = fmaf(c2[k], Wc3[k * 4 + t], s);
        logits[b * 4 + t] = s;
    }
}

// ---------------------------------------------------------------------------
// Launch
// ---------------------------------------------------------------------------
extern "C" void kernel_launch(void* const* d_in, const int* in_sizes, int n_in,
                              void* d_out, int out_size)
{
    const float* A   = (const float*)d_in[0];   // sc_matrix [B,N,N]
    const float* W1  = (const float*)d_in[1];
    const float* b1  = (const float*)d_in[2];
    const float* W2  = (const float*)d_in[3];
    const float* b2  = (const float*)d_in[4];
    const float* lng = (const float*)d_in[5];
    const float* lnb = (const float*)d_in[6];
    const float* Wc1 = (const float*)d_in[7];
    const float* bc1 = (const float*)d_in[8];
    const float* g1  = (const float*)d_in[9];
    const float* t1p = (const float*)d_in[10];
    const float* Wc2 = (const float*)d_in[11];
    const float* bc2 = (const float*)d_in[12];
    const float* g2  = (const float*)d_in[13];
    const float* t2p = (const float*)d_in[14];
    const float* Wc3 = (const float*)d_in[15];
    const float* bc3 = (const float*)d_in[16];

    float* out    = (float*)d_out;
    float* logits = out;                 // [32,4]
    float* zp     = out + BATCH * 4;     // [32,512]

    void *p0, *p1, *pd, *pp;
    cudaGetSymbolAddress(&p0, g_buf0);
    cudaGetSymbolAddress(&p1, g_buf1);
    cudaGetSymbolAddress(&pd, g_dis);
    cudaGetSymbolAddress(&pp, g_partial);
    float* buf0    = (float*)p0;
    float* buf1    = (float*)p1;
    float* dis     = (float*)pd;
    float* partial = (float*)pp;

    const long MN = (long)NN * NN;   // per-batch A stride
    const long MD = (long)NN * DD;   // per-batch feature stride

    // 1) dis = rsqrt(colsum(A))
    deg_kernel<<<dim3(NN / 256, BATCH), 256>>>(A, dis);

    // 2) buf0 = dis ⊙ (x @ W1)   — flat GEMM M=32768,K=1024,N=512
    gemm_k<0, 0><<<dim3(DD / BN, (BATCH * NN) / BM, 1), 256>>>(
        A, W1, buf0, NN, NN, DD, DD, 0, 0, 0, dis, 0, nullptr);

    // 3) buf1 = relu(dis ⊙ (A^T @ buf0) + b1)  — batched
    gemm_k<1, 1><<<dim3(DD / BN, NN / BM, BATCH), 256>>>(
        A, buf0, buf1, NN, NN, DD, DD, MN, MD, MD, dis, NN, b1);

    // 4) buf0 = dis ⊙ (buf1 @ W2)  — flat, K=512
    gemm_k<0, 0><<<dim3(DD / BN, (BATCH * NN) / BM, 1), 256>>>(
        buf1, W2, buf0, DD, DD, DD, DD, 0, 0, 0, dis, 0, nullptr);

    // 5) buf1 = dis ⊙ (A^T @ buf0) + b2  (= h2) — batched
    gemm_k<1, 2><<<dim3(DD / BN, NN / BM, BATCH), 256>>>(
        A, buf0, buf1, NN, NN, DD, DD, MN, MD, MD, dis, NN, b2);

    // 6) LayerNorm + mean-pool (two deterministic stages)
    ln_pool_partial<<<dim3(8, BATCH), 256>>>(buf1, lng, lnb, partial);
    pool_finalize<<<BATCH, DD>>>(partial, zp);

    // 7) classifier head
    classifier_kernel<<<BATCH, 128>>>(zp, Wc1, bc1, g1, t1p,
                                      Wc2, bc2, g2, t2p, Wc3, bc3, logits);
}

// round 9
// speedup vs baseline: 2.4522x; 2.4522x over previous
#include <cuda_runtime.h>
#include <cuda_bf16.h>
#include <cstdint>

#define BATCH 32
#define NN    1024
#define DD    512
#define LN_EPS 1e-5f

// ------------------------- scratch (device globals) -------------------------
__device__ __nv_bfloat16 g_Ah [(size_t)BATCH * NN * NN];
__device__ __nv_bfloat16 g_Al [(size_t)BATCH * NN * NN];
__device__ __nv_bfloat16 g_ATh[(size_t)BATCH * NN * NN];
__device__ __nv_bfloat16 g_ATl[(size_t)BATCH * NN * NN];
__device__ __nv_bfloat16 g_W1Th[(size_t)DD * NN];
__device__ __nv_bfloat16 g_W1Tl[(size_t)DD * NN];
__device__ __nv_bfloat16 g_W2Th[(size_t)DD * DD];
__device__ __nv_bfloat16 g_W2Tl[(size_t)DD * DD];
__device__ __nv_bfloat16 g_t1Th[(size_t)BATCH * DD * NN];
__device__ __nv_bfloat16 g_t1Tl[(size_t)BATCH * DD * NN];
__device__ __nv_bfloat16 g_h1h [(size_t)BATCH * NN * DD];
__device__ __nv_bfloat16 g_h1l [(size_t)BATCH * NN * DD];
__device__ __nv_bfloat16 g_t2Th[(size_t)BATCH * DD * NN];
__device__ __nv_bfloat16 g_t2Tl[(size_t)BATCH * DD * NN];
__device__ float g_h2[(size_t)BATCH * NN * DD];
__device__ float g_dis[BATCH * NN];
__device__ float g_partial[BATCH * 8 * DD];

// ------------------------------ PTX helpers ---------------------------------
static __device__ __forceinline__ uint32_t s2u(const void* p) {
    uint32_t a;
    asm("{ .reg .u64 t; cvta.to.shared.u64 t, %1; cvt.u32.u64 %0, t; }" : "=r"(a) : "l"(p));
    return a;
}
static __device__ __forceinline__ uint32_t swz(uint32_t o) { return o ^ ((o >> 3) & 0x70u); }
static __device__ __forceinline__ void cp16(uint32_t s, const void* g) {
    asm volatile("cp.async.cg.shared.global [%0], [%1], 16;" :: "r"(s), "l"(g));
}
static __device__ __forceinline__ void cp_commit() { asm volatile("cp.async.commit_group;"); }
template<int N> static __device__ __forceinline__ void cp_wait() {
    asm volatile("cp.async.wait_group %0;" :: "n"(N));
}
static __device__ __forceinline__ void ldm4(uint32_t* r, uint32_t a) {
    asm volatile("ldmatrix.sync.aligned.m8n8.x4.shared.b16 {%0,%1,%2,%3}, [%4];"
                 : "=r"(r[0]), "=r"(r[1]), "=r"(r[2]), "=r"(r[3]) : "r"(a));
}
static __device__ __forceinline__ void mma16816(float* c, const uint32_t* a,
                                                uint32_t b0, uint32_t b1) {
    asm volatile(
        "mma.sync.aligned.m16n8k16.row.col.f32.bf16.bf16.f32 "
        "{%0,%1,%2,%3}, {%4,%5,%6,%7}, {%8,%9}, {%0,%1,%2,%3};"
        : "+f"(c[0]), "+f"(c[1]), "+f"(c[2]), "+f"(c[3])
        : "r"(a[0]), "r"(a[1]), "r"(a[2]), "r"(a[3]), "r"(b0), "r"(b1));
}
#define GEMM_SMEM (3 * 32768 + 1024)

// ---------------------------------------------------------------------------
__global__ void deg_kernel(const float* __restrict__ A, float* __restrict__ dis)
{
    int b = blockIdx.y;
    int j = blockIdx.x * 256 + threadIdx.x;
    const float* Ab = A + (size_t)b * NN * NN;
    float s = 0.f;
#pragma unroll 8
    for (int i = 0; i < NN; i++) s += Ab[(size_t)i * NN + j];
    dis[b * NN + j] = (s > 0.f) ? rsqrtf(s) : 0.f;
}

// fp32 src[z][R][C] -> transposed split th/tl [z][C][R]; optional direct dh/dl
template<bool DIRECT>
__global__ void tsplit(const float* __restrict__ src,
                       __nv_bfloat16* __restrict__ th, __nv_bfloat16* __restrict__ tl,
                       __nv_bfloat16* __restrict__ dh, __nv_bfloat16* __restrict__ dl,
                       int R, int C)
{
    __shared__ float tile[32][33];
    int z = blockIdx.z;
    size_t base = (size_t)z * R * C;
    int c0 = blockIdx.x * 32, r0 = blockIdx.y * 32;
    int tx = threadIdx.x, ty = threadIdx.y;
#pragma unroll
    for (int i = 0; i < 4; i++) {
        int r = r0 + ty + i * 8;
        float v = src[base + (size_t)r * C + c0 + tx];
        tile[ty + i * 8][tx] = v;
        if (DIRECT) {
            __nv_bfloat16 h = __float2bfloat16(v);
            dh[base + (size_t)r * C + c0 + tx] = h;
            dl[base + (size_t)r * C + c0 + tx] = __float2bfloat16(v - __bfloat162float(h));
        }
    }
    __syncthreads();
#pragma unroll
    for (int i = 0; i < 4; i++) {
        int cc = c0 + ty + i * 8;
        float v = tile[tx][ty + i * 8];
        __nv_bfloat16 h = __float2bfloat16(v);
        th[base + (size_t)cc * R + r0 + tx] = h;
        tl[base + (size_t)cc * R + r0 + tx] = __float2bfloat16(v - __bfloat162float(h));
    }
}

// ---------------------------------------------------------------------------
// mma.sync GEMM: D[128,128] = sum_k Aop[m,k]*Bop[n,k], 3-phase bf16 split.
// 8 warps (4 m x 2 n), warp tile 32x64, m16n8k16 HMMA, cp.async 3-stage ring.
// EPI 0: v=acc*dis[m], split bf16, TRANSPOSED out [batch][n][node] (flat M)
// EPI 1: v=relu(acc*dis[m]+bias[n]), split bf16, direct (batched via z)
// EPI 2: v=acc*dis[m]+bias[n], fp32, direct (batched via z)
// ---------------------------------------------------------------------------
template<int EPI>
__global__ void __launch_bounds__(256, 2) tc_gemm(
    const __nv_bfloat16* __restrict__ Ah, const __nv_bfloat16* __restrict__ Al,
    const __nv_bfloat16* __restrict__ Bh, const __nv_bfloat16* __restrict__ Bl,
    void* __restrict__ outH, void* __restrict__ outL,
    int K, long sA, long sB, long sC,
    const float* __restrict__ dis, int disStride,
    const float* __restrict__ bias)
{
    extern __shared__ char dsm[];
    uint32_t raw = s2u(dsm);
    uint32_t sbase = (raw + 1023u) & ~1023u;

    const int tid = threadIdx.x;
    const int z  = blockIdx.z;
    const int m0 = blockIdx.y * 128;
    const int n0 = blockIdx.x * 128;
    const int wid = tid >> 5, lane = tid & 31;
    const int mr = (wid & 3) * 32;      // warp m offset in tile
    const int nc = (wid >> 2) * 64;     // warp n offset in tile

    const __nv_bfloat16* Ahz = Ah + (size_t)z * sA;
    const __nv_bfloat16* Alz = Al + (size_t)z * sA;
    const __nv_bfloat16* Bhz = Bh + (size_t)z * sB;
    const __nv_bfloat16* Blz = Bl + (size_t)z * sB;
    const __nv_bfloat16* AP[3] = { Ahz, Ahz, Alz };
    const __nv_bfloat16* BP[3] = { Bhz, Blz, Bhz };

    const int SP = K >> 6;       // 64-elem K stages per phase
    const int NS = 3 * SP;

    auto load_stage = [&](int t, int buf) {
        int p  = t / SP;
        int kk = (t - p * SP) << 6;
        const __nv_bfloat16* Ap = AP[p];
        const __nv_bfloat16* Bp = BP[p];
        uint32_t sb = sbase + buf * 32768;
#pragma unroll
        for (int i = 0; i < 8; i++) {
            int c = tid + (i << 8);          // 0..2047 16B chunks
            int r = (c >> 3) & 127;
            int col = c & 7;
            if (c >= 1024)
                cp16(sb + 16384u + swz((uint32_t)(r * 128 + col * 16)),
                     Bp + (size_t)(n0 + r) * K + kk + col * 8);
            else
                cp16(sb + swz((uint32_t)(r * 128 + col * 16)),
                     Ap + (size_t)(m0 + r) * K + kk + col * 8);
        }
        cp_commit();
    };

    load_stage(0, 0);
    load_stage(1, 1);
    load_stage(2, 2);

    float acc[2][8][4];
#pragma unroll
    for (int mi = 0; mi < 2; mi++)
#pragma unroll
        for (int ni = 0; ni < 8; ni++)
#pragma unroll
            for (int e = 0; e < 4; e++) acc[mi][ni][e] = 0.f;

    // per-lane ldmatrix row/byte offsets (within tile)
    const int a_row = mr + (lane & 15);
    const int a_kb  = ((lane >> 4) & 1) * 16;
    const int b_row = (lane & 7) + ((lane & 16) ? 8 : 0);
    const int b_kb  = (lane & 8) ? 16 : 0;

    for (int s = 0; s < NS; s++) {
        if (s <= NS - 3)      cp_wait<2>();
        else if (s == NS - 2) cp_wait<1>();
        else                  cp_wait<0>();
        __syncthreads();

        uint32_t abase = sbase + (s % 3) * 32768;
        uint32_t bbase = abase + 16384u;
#pragma unroll
        for (int ks = 0; ks < 4; ks++) {
            int kb = ks * 32;
            uint32_t a[2][4], b[4][4];
#pragma unroll
            for (int mi = 0; mi < 2; mi++)
                ldm4(a[mi], abase + swz((uint32_t)((a_row + mi * 16) * 128 + kb + a_kb)));
#pragma unroll
            for (int g = 0; g < 4; g++)
                ldm4(b[g], bbase + swz((uint32_t)((nc + g * 16 + b_row) * 128 + kb + b_kb)));
#pragma unroll
            for (int mi = 0; mi < 2; mi++)
#pragma unroll
                for (int g = 0; g < 4; g++) {
                    mma16816(acc[mi][g * 2 + 0], a[mi], b[g][0], b[g][1]);
                    mma16816(acc[mi][g * 2 + 1], a[mi], b[g][2], b[g][3]);
                }
        }
        __syncthreads();
        if (s + 3 < NS) load_stage(s + 3, s % 3);
    }

    // ---- epilogue ----
    // frag (mi,ni): rows r0 = mr+mi*16+(lane>>2), r1 = r0+8;
    //               cols cb = nc+ni*8+(lane&3)*2, cb+1
    float sc[4];
#pragma unroll
    for (int mi = 0; mi < 2; mi++) {
        sc[mi * 2 + 0] = dis[z * disStride + m0 + mr + mi * 16 + (lane >> 2)];
        sc[mi * 2 + 1] = dis[z * disStride + m0 + mr + mi * 16 + (lane >> 2) + 8];
    }

    if (EPI == 0) {
        float* sf = (float*)(dsm + (sbase - raw));   // [128 cols][pitch 132] -> sf[col*132+row]
#pragma unroll
        for (int mi = 0; mi < 2; mi++)
#pragma unroll
            for (int ni = 0; ni < 8; ni++) {
                int r0 = mr + mi * 16 + (lane >> 2);
                int cb = nc + ni * 8 + (lane & 3) * 2;
                sf[(cb + 0) * 132 + r0]     = acc[mi][ni][0] * sc[mi * 2];
                sf[(cb + 1) * 132 + r0]     = acc[mi][ni][1] * sc[mi * 2];
                sf[(cb + 0) * 132 + r0 + 8] = acc[mi][ni][2] * sc[mi * 2 + 1];
                sf[(cb + 1) * 132 + r0 + 8] = acc[mi][ni][3] * sc[mi * 2 + 1];
            }
        __syncthreads();
        int batch = m0 >> 10, node0 = m0 & 1023;
        int n = tid >> 1, half = tid & 1;
        size_t off = (size_t)batch * DD * NN + (size_t)(n0 + n) * NN + node0 + half * 64;
        __nv_bfloat16* oh = (__nv_bfloat16*)outH + off;
        __nv_bfloat16* ol = (__nv_bfloat16*)outL + off;
        const float* src = sf + (size_t)n * 132 + half * 64;
#pragma unroll
        for (int j = 0; j < 8; j++) {
            __nv_bfloat16 hv[8], lv[8];
#pragma unroll
            for (int e = 0; e < 8; e++) {
                float v = src[j * 8 + e];
                hv[e] = __float2bfloat16(v);
                lv[e] = __float2bfloat16(v - __bfloat162float(hv[e]));
            }
            *(uint4*)(oh + j * 8) = *(const uint4*)hv;
            *(uint4*)(ol + j * 8) = *(const uint4*)lv;
        }
    } else if (EPI == 1) {
        __nv_bfloat16* oh = (__nv_bfloat16*)outH + (size_t)z * sC;
        __nv_bfloat16* ol = (__nv_bfloat16*)outL + (size_t)z * sC;
#pragma unroll
        for (int mi = 0; mi < 2; mi++)
#pragma unroll
            for (int ni = 0; ni < 8; ni++) {
                int cb = n0 + nc + ni * 8 + (lane & 3) * 2;
                float bb0 = bias[cb], bb1 = bias[cb + 1];
#pragma unroll
                for (int hfl = 0; hfl < 2; hfl++) {
                    int row = m0 + mr + mi * 16 + (lane >> 2) + hfl * 8;
                    float v0 = fmaxf(fmaf(acc[mi][ni][hfl * 2 + 0], sc[mi * 2 + hfl], bb0), 0.f);
                    float v1 = fmaxf(fmaf(acc[mi][ni][hfl * 2 + 1], sc[mi * 2 + hfl], bb1), 0.f);
                    __nv_bfloat16 h0 = __float2bfloat16(v0), h1 = __float2bfloat16(v1);
                    __nv_bfloat16 l0 = __float2bfloat16(v0 - __bfloat162float(h0));
                    __nv_bfloat16 l1 = __float2bfloat16(v1 - __bfloat162float(h1));
                    *(__nv_bfloat162*)(oh + (size_t)row * DD + cb) = __nv_bfloat162(h0, h1);
                    *(__nv_bfloat162*)(ol + (size_t)row * DD + cb) = __nv_bfloat162(l0, l1);
                }
            }
    } else {
        float* o = (float*)outH + (size_t)z * sC;
#pragma unroll
        for (int mi = 0; mi < 2; mi++)
#pragma unroll
            for (int ni = 0; ni < 8; ni++) {
                int cb = n0 + nc + ni * 8 + (lane & 3) * 2;
                float bb0 = bias[cb], bb1 = bias[cb + 1];
#pragma unroll
                for (int hfl = 0; hfl < 2; hfl++) {
                    int row = m0 + mr + mi * 16 + (lane >> 2) + hfl * 8;
                    float2 v;
                    v.x = fmaf(acc[mi][ni][hfl * 2 + 0], sc[mi * 2 + hfl], bb0);
                    v.y = fmaf(acc[mi][ni][hfl * 2 + 1], sc[mi * 2 + hfl], bb1);
                    *(float2*)(o + (size_t)row * DD + cb) = v;
                }
            }
    }
}

// ---------------------------------------------------------------------------
__global__ void ln_pool_partial(const float* __restrict__ h2,
                                const float* __restrict__ lng,
                                const float* __restrict__ lnb,
                                float* __restrict__ partial)
{
    int b = blockIdx.y, ch = blockIdx.x;
    int w = threadIdx.x >> 5, l = threadIdx.x & 31;
    const float* base = h2 + ((size_t)b * NN + ch * 128) * DD;
    float accv[16];
#pragma unroll
    for (int c = 0; c < 16; c++) accv[c] = 0.f;
    for (int r = w; r < 128; r += 8) {
        const float* row = base + (size_t)r * DD;
        float x[16], s = 0.f;
#pragma unroll
        for (int c = 0; c < 16; c++) { x[c] = row[l + 32 * c]; s += x[c]; }
#pragma unroll
        for (int o = 16; o; o >>= 1) s += __shfl_xor_sync(0xffffffffu, s, o);
        float mu = s * (1.f / DD), s2 = 0.f;
#pragma unroll
        for (int c = 0; c < 16; c++) { float d = x[c] - mu; s2 += d * d; }
#pragma unroll
        for (int o = 16; o; o >>= 1) s2 += __shfl_xor_sync(0xffffffffu, s2, o);
        float rstd = rsqrtf(s2 * (1.f / DD) + LN_EPS);
#pragma unroll
        for (int c = 0; c < 16; c++) accv[c] += (x[c] - mu) * rstd;
    }
    __shared__ float wacc[8][DD];
#pragma unroll
    for (int c = 0; c < 16; c++) wacc[w][l + 32 * c] = accv[c];
    __syncthreads();
    for (int d = threadIdx.x; d < DD; d += 256) {
        float s = 0.f;
#pragma unroll
        for (int w2 = 0; w2 < 8; w2++) s += wacc[w2][d];
        partial[((size_t)b * 8 + ch) * DD + d] = lng[d] * s + 128.f * lnb[d];
    }
}

__global__ void pool_finalize(const float* __restrict__ partial, float* __restrict__ zp)
{
    int b = blockIdx.x, d = threadIdx.x;
    float s = 0.f;
#pragma unroll
    for (int c = 0; c < 8; c++) s += partial[((size_t)b * 8 + c) * DD + d];
    zp[b * DD + d] = s * (1.f / NN);
}

__device__ __forceinline__ float blk_sum128(float v, volatile float* red)
{
    int t = threadIdx.x;
    red[t] = v; __syncthreads();
#pragma unroll
    for (int o = 64; o > 0; o >>= 1) { if (t < o) red[t] += red[t + o]; __syncthreads(); }
    float s = red[0]; __syncthreads();
    return s;
}

__global__ void classifier_kernel(
    const float* __restrict__ zp_all,
    const float* __restrict__ Wc1, const float* __restrict__ bc1,
    const float* __restrict__ g1,  const float* __restrict__ t1p,
    const float* __restrict__ Wc2, const float* __restrict__ bc2,
    const float* __restrict__ g2,  const float* __restrict__ t2p,
    const float* __restrict__ Wc3, const float* __restrict__ bc3,
    float* __restrict__ logits)
{
    int b = blockIdx.x, t = threadIdx.x;
    __shared__ float zp[DD], c1[128], c2[64], red[128];
    for (int d = t; d < DD; d += 128) zp[d] = zp_all[b * DD + d];
    __syncthreads();
    float v = 0.f;
#pragma unroll 4
    for (int k = 0; k < DD; k++) v = fmaf(zp[k], Wc1[k * 128 + t], v);
    v += bc1[t];
    float mu = blk_sum128(v, red) * (1.f / 128.f);
    float d1 = v - mu;
    float var = blk_sum128(d1 * d1, red) * (1.f / 128.f);
    v = fmaxf(d1 * rsqrtf(var + LN_EPS) * g1[t] + t1p[t], 0.f);
    c1[t] = v; __syncthreads();
    float v2 = 0.f;
    if (t < 64) {
#pragma unroll 4
        for (int k = 0; k < 128; k++) v2 = fmaf(c1[k], Wc2[k * 64 + t], v2);
        v2 += bc2[t];
    }
    float mu2 = blk_sum128((t < 64) ? v2 : 0.f, red) * (1.f / 64.f);
    float d2 = (t < 64) ? (v2 - mu2) : 0.f;
    float var2 = blk_sum128(d2 * d2, red) * (1.f / 64.f);
    if (t < 64) c2[t] = fmaxf(d2 * rsqrtf(var2 + LN_EPS) * g2[t] + t2p[t], 0.f);
    __syncthreads();
    if (t < 4) {
        float s = bc3[t];
#pragma unroll
        for (int k = 0; k < 64; k++) s = fmaf(c2[k], Wc3[k * 4 + t], s);
        logits[b * 4 + t] = s;
    }
}

// ---------------------------------------------------------------------------
extern "C" void kernel_launch(void* const* d_in, const int* in_sizes, int n_in,
                              void* d_out, int out_size)
{
    const float* A   = (const float*)d_in[0];
    const float* W1  = (const float*)d_in[1];
    const float* b1  = (const float*)d_in[2];
    const float* W2  = (const float*)d_in[3];
    const float* b2  = (const float*)d_in[4];
    const float* lng = (const float*)d_in[5];
    const float* lnb = (const float*)d_in[6];
    const float* Wc1 = (const float*)d_in[7];
    const float* bc1 = (const float*)d_in[8];
    const float* g1  = (const float*)d_in[9];
    const float* t1p = (const float*)d_in[10];
    const float* Wc2 = (const float*)d_in[11];
    const float* bc2 = (const float*)d_in[12];
    const float* g2  = (const float*)d_in[13];
    const float* t2p = (const float*)d_in[14];
    const float* Wc3 = (const float*)d_in[15];
    const float* bc3 = (const float*)d_in[16];

    float* out    = (float*)d_out;
    float* logits = out;
    float* zp     = out + BATCH * 4;

    void *pAh, *pAl, *pATh, *pATl, *pW1h, *pW1l, *pW2h, *pW2l,
         *pt1h, *pt1l, *ph1h, *ph1l, *pt2h, *pt2l, *ph2, *pd, *pp;
    cudaGetSymbolAddress(&pAh, g_Ah);   cudaGetSymbolAddress(&pAl, g_Al);
    cudaGetSymbolAddress(&pATh, g_ATh); cudaGetSymbolAddress(&pATl, g_ATl);
    cudaGetSymbolAddress(&pW1h, g_W1Th); cudaGetSymbolAddress(&pW1l, g_W1Tl);
    cudaGetSymbolAddress(&pW2h, g_W2Th); cudaGetSymbolAddress(&pW2l, g_W2Tl);
    cudaGetSymbolAddress(&pt1h, g_t1Th); cudaGetSymbolAddress(&pt1l, g_t1Tl);
    cudaGetSymbolAddress(&ph1h, g_h1h);  cudaGetSymbolAddress(&ph1l, g_h1l);
    cudaGetSymbolAddress(&pt2h, g_t2Th); cudaGetSymbolAddress(&pt2l, g_t2Tl);
    cudaGetSymbolAddress(&ph2, g_h2);
    cudaGetSymbolAddress(&pd, g_dis);    cudaGetSymbolAddress(&pp, g_partial);

    __nv_bfloat16 *Ah = (__nv_bfloat16*)pAh, *Al = (__nv_bfloat16*)pAl;
    __nv_bfloat16 *ATh = (__nv_bfloat16*)pATh, *ATl = (__nv_bfloat16*)pATl;
    __nv_bfloat16 *W1h = (__nv_bfloat16*)pW1h, *W1l = (__nv_bfloat16*)pW1l;
    __nv_bfloat16 *W2h = (__nv_bfloat16*)pW2h, *W2l = (__nv_bfloat16*)pW2l;
    __nv_bfloat16 *t1h = (__nv_bfloat16*)pt1h, *t1l = (__nv_bfloat16*)pt1l;
    __nv_bfloat16 *h1h = (__nv_bfloat16*)ph1h, *h1l = (__nv_bfloat16*)ph1l;
    __nv_bfloat16 *t2h = (__nv_bfloat16*)pt2h, *t2l = (__nv_bfloat16*)pt2l;
    float *h2 = (float*)ph2, *dis = (float*)pd, *partial = (float*)pp;

    cudaFuncSetAttribute(tc_gemm<0>, cudaFuncAttributeMaxDynamicSharedMemorySize, GEMM_SMEM);
    cudaFuncSetAttribute(tc_gemm<1>, cudaFuncAttributeMaxDynamicSharedMemorySize, GEMM_SMEM);
    cudaFuncSetAttribute(tc_gemm<2>, cudaFuncAttributeMaxDynamicSharedMemorySize, GEMM_SMEM);

    const long MN = (long)NN * NN, MDN = (long)DD * NN, MND = (long)NN * DD;

    // 1) dis
    deg_kernel<<<dim3(NN / 256, BATCH), 256>>>(A, dis);
    // 2) split A (direct + transposed), W1^T, W2^T
    tsplit<true><<<dim3(32, 32, 32), dim3(32, 8)>>>(A, ATh, ATl, Ah, Al, NN, NN);
    tsplit<false><<<dim3(DD / 32, NN / 32, 1), dim3(32, 8)>>>(W1, W1h, W1l, nullptr, nullptr, NN, DD);
    tsplit<false><<<dim3(DD / 32, DD / 32, 1), dim3(32, 8)>>>(W2, W2h, W2l, nullptr, nullptr, DD, DD);

    // 3) t1^T = (dis ⊙ (x @ W1))^T, split
    tc_gemm<0><<<dim3(4, 256, 1), 256, GEMM_SMEM>>>(
        Ah, Al, W1h, W1l, t1h, t1l, NN, 0, 0, 0, dis, 0, nullptr);
    // 4) h1 = relu(dis ⊙ (A^T @ t1) + b1), split
    tc_gemm<1><<<dim3(4, 8, BATCH), 256, GEMM_SMEM>>>(
        ATh, ATl, t1h, t1l, h1h, h1l, NN, MN, MDN, MND, dis, NN, b1);
    // 5) t2^T = (dis ⊙ (h1 @ W2))^T, split
    tc_gemm<0><<<dim3(4, 256, 1), 256, GEMM_SMEM>>>(
        h1h, h1l, W2h, W2l, t2h, t2l, DD, 0, 0, 0, dis, 0, nullptr);
    // 6) h2 = dis ⊙ (A^T @ t2) + b2, fp32
    tc_gemm<2><<<dim3(4, 8, BATCH), 256, GEMM_SMEM>>>(
        ATh, ATl, t2h, t2l, h2, nullptr, NN, MN, MDN, MND, dis, NN, b2);

    // 7) LN + pool + classifier
    ln_pool_partial<<<dim3(8, BATCH), 256>>>(h2, lng, lnb, partial);
    pool_finalize<<<BATCH, DD>>>(partial, zp);
    classifier_kernel<<<BATCH, 128>>>(zp, Wc1, bc1, g1, t1p,
                                      Wc2, bc2, g2, t2p, Wc3, bc3, logits);
}